// round 5
// baseline (speedup 1.0000x reference)
#include <cuda_runtime.h>
#include <math.h>
#include <stdint.h>

#define B_ROWS 16384
#define C_CLS  1000
#define F_DIM  256

#define BM 128
#define BN 128
#define BK 32
#define NCHUNK (F_DIM / BK)   // 8
#define LDA 36                // smem row stride in floats (pad 4)
#define TILE_FLOATS (128 * LDA)   // 4608 floats per tile
#define BUF_FLOATS  (2 * TILE_FLOATS)
#define PARAM_OFF   (2 * BUF_FLOATS)          // after double buffers
#define SMEM_FLOATS (PARAM_OFF + 512)
#define SMEM_BYTES  (SMEM_FLOATS * 4)         // 75776

// ---- device scratch ----
__device__ float g_fr[(size_t)B_ROWS * F_DIM];   // tf32-rounded features
__device__ float g_mr[(size_t)C_CLS * F_DIM];    // tf32-rounded mean_vecs
__device__ float g_scores[(size_t)B_ROWS * C_CLS];
__device__ float g_f2[B_ROWS];
__device__ float g_m2[C_CLS];

__device__ __forceinline__ uint32_t smem_u32(const void* p) {
    uint32_t a;
    asm("{ .reg .u64 t; cvta.to.shared.u64 t, %1; cvt.u32.u64 %0, t; }" : "=r"(a) : "l"(p));
    return a;
}
__device__ __forceinline__ void cp16(uint32_t daddr, const void* src, uint32_t bytes) {
    asm volatile("cp.async.ca.shared.global [%0], [%1], 16, %2;"
                 :: "r"(daddr), "l"(src), "r"(bytes) : "memory");
}
__device__ __forceinline__ float tf32_round(float x) {
    uint32_t u;
    asm("cvt.rna.tf32.f32 %0, %1;" : "=r"(u) : "f"(x));
    return __uint_as_float(u);
}
__device__ __forceinline__ void mma_tf32(float* d, const uint32_t* a, const uint32_t* b) {
    asm volatile(
        "mma.sync.aligned.m16n8k8.row.col.f32.tf32.tf32.f32 "
        "{%0,%1,%2,%3}, {%4,%5,%6,%7}, {%8,%9}, {%0,%1,%2,%3};"
        : "+f"(d[0]), "+f"(d[1]), "+f"(d[2]), "+f"(d[3])
        : "r"(a[0]), "r"(a[1]), "r"(a[2]), "r"(a[3]), "r"(b[0]), "r"(b[1]));
}

// -------------------------------------------------------------------------
// Convert fp32 -> tf32-rounded fp32 and row sum-of-squares. One warp/row.
// -------------------------------------------------------------------------
__global__ void convert_kernel(const float* __restrict__ x,
                               float* __restrict__ xr_out,
                               float* __restrict__ sq, int rows) {
    int warp = (blockIdx.x * blockDim.x + threadIdx.x) >> 5;
    int lane = threadIdx.x & 31;
    if (warp >= rows) return;
    const float* xr = x + (size_t)warp * F_DIM;
    float s = 0.f;
#pragma unroll
    for (int i = 0; i < 2; i++) {
        int e = (lane + i * 32) * 4;
        float4 v = *(const float4*)(xr + e);
        s += v.x * v.x + v.y * v.y + v.z * v.z + v.w * v.w;
        float4 o;
        o.x = tf32_round(v.x); o.y = tf32_round(v.y);
        o.z = tf32_round(v.z); o.w = tf32_round(v.w);
        *(float4*)(xr_out + (size_t)warp * F_DIM + e) = o;
    }
#pragma unroll
    for (int o = 16; o; o >>= 1) s += __shfl_xor_sync(0xffffffffu, s, o);
    if (lane == 0) sq[warp] = s;
}

// -------------------------------------------------------------------------
// tf32 mma.sync GEMM (features @ mean_vecs^T) + fused OpenMax epilogue.
// 256 threads, CTA tile 128x128, BK=32, double-buffered cp.async.
// NOTE: no min-blocks hint -> ptxas free to use up to 255 regs (no spills).
// -------------------------------------------------------------------------
__global__ void __launch_bounds__(256)
gemm_openmax_tc(const float* __restrict__ logits,
                const float* __restrict__ wshape,
                const float* __restrict__ wloc,
                const float* __restrict__ wscale) {
    extern __shared__ float smem[];
    const uint32_t sb = smem_u32(smem);
    const int tid = threadIdx.x;
    const int lane = tid & 31;
    const int wid = tid >> 5;
    const int wm = wid & 1;    // warp row (2 x 64)
    const int wn = wid >> 1;   // warp col (4 x 32)
    const int rowBase = blockIdx.y * BM;
    const int colBase = blockIdx.x * BN;

    float* m2s  = smem + PARAM_OFF;
    float* shs  = m2s + 128;
    float* lcs  = shs + 128;
    float* iscs = lcs + 128;
    if (tid < 128) {
        int gc = colBase + tid;
        int cc = (gc < C_CLS) ? gc : 0;
        m2s[tid] = g_m2[cc];
        shs[tid] = wshape[cc];
        lcs[tid] = wloc[cc];
        iscs[tid] = 1.f / wscale[cc];
    }

    float acc[4][4][4];
#pragma unroll
    for (int i = 0; i < 4; i++)
#pragma unroll
        for (int j = 0; j < 4; j++)
#pragma unroll
            for (int q = 0; q < 4; q++) acc[i][j][q] = 0.f;

    // ---- async load of one K-chunk into buffer `buf` ----
    auto loadChunk = [&](int ch, int buf) {
        const int k0 = ch * BK;
        const uint32_t sa = sb + (uint32_t)buf * BUF_FLOATS * 4;
        const uint32_t sbB = sa + TILE_FLOATS * 4;
#pragma unroll
        for (int it = 0; it < 4; it++) {
            int idx = tid + it * 256;
            int r = idx >> 3;
            int c4 = (idx & 7) * 4;
            const float* gA = g_fr + (size_t)(rowBase + r) * F_DIM + k0 + c4;
            cp16(sa + (uint32_t)(r * LDA + c4) * 4, gA, 16u);
            int gc = colBase + r;
            const float* gB = g_mr + (size_t)((gc < C_CLS) ? gc : 0) * F_DIM + k0 + c4;
            cp16(sbB + (uint32_t)(r * LDA + c4) * 4, gB, (gc < C_CLS) ? 16u : 0u);
        }
        asm volatile("cp.async.commit_group;" ::: "memory");
    };

    loadChunk(0, 0);

    const int r0 = wm * 64 + (lane >> 2);
    const int c0 = wn * 32 + (lane >> 2);
    const int kq = lane & 3;

#pragma unroll 1
    for (int ch = 0; ch < NCHUNK; ch++) {
        if (ch + 1 < NCHUNK) {
            loadChunk(ch + 1, (ch + 1) & 1);
            asm volatile("cp.async.wait_group 1;" ::: "memory");
        } else {
            asm volatile("cp.async.wait_group 0;" ::: "memory");
        }
        __syncthreads();

        const float* A = smem + (ch & 1) * BUF_FLOATS;
        const float* Bs = A + TILE_FLOATS;
#pragma unroll
        for (int ks = 0; ks < 4; ks++) {
            const int kb = ks * 8 + kq;
            uint32_t a[4][4], b[4][2];
#pragma unroll
            for (int ma = 0; ma < 4; ma++) {
                const float* ap = A + (r0 + ma * 16) * LDA + kb;
                a[ma][0] = __float_as_uint(ap[0]);
                a[ma][1] = __float_as_uint(ap[8 * LDA]);
                a[ma][2] = __float_as_uint(ap[4]);
                a[ma][3] = __float_as_uint(ap[8 * LDA + 4]);
            }
#pragma unroll
            for (int na = 0; na < 4; na++) {
                const float* bp = Bs + (c0 + na * 8) * LDA + kb;
                b[na][0] = __float_as_uint(bp[0]);
                b[na][1] = __float_as_uint(bp[4]);
            }
#pragma unroll
            for (int ma = 0; ma < 4; ma++)
#pragma unroll
                for (int na = 0; na < 4; na++)
                    mma_tf32(acc[ma][na], a[ma], b[na]);
        }
        __syncthreads();
    }

    // ---- fused OpenMax epilogue ----
    const int lq = lane & 3;
    const int lr = lane >> 2;
#pragma unroll
    for (int ma = 0; ma < 4; ma++) {
#pragma unroll
        for (int h = 0; h < 2; h++) {
            const int grow = rowBase + wm * 64 + ma * 16 + lr + h * 8;
            const float f2v = g_f2[grow];
            const float* lrow = logits + (size_t)grow * C_CLS;
            float* srow = g_scores + (size_t)grow * C_CLS;
#pragma unroll
            for (int na = 0; na < 4; na++) {
                const int col = wn * 32 + na * 8 + 2 * lq;
                const int gc = colBase + col;
                if (gc >= C_CLS) continue;   // C even -> pair fully in/out
                float2 lg = *(const float2*)(lrow + gc);
                float2 outp;
                float dots[2] = { acc[ma][na][h * 2], acc[ma][na][h * 2 + 1] };
                float lgv[2] = { lg.x, lg.y };
                float res[2];
#pragma unroll
                for (int q = 0; q < 2; q++) {
                    const int c = col + q;
                    float d2 = f2v + m2s[c] - 2.f * dots[q];
                    float dist = sqrtf(fmaxf(d2, 1e-12f));
                    float xp = (dist - lcs[c]) * iscs[c];
                    float wv = 0.f;
                    if (xp > 0.f) {
                        float p = exp2f(shs[c] * __log2f(xp));
                        wv = 1.f - __expf(-p);
                    }
                    float w2 = wv * wv;
                    float w4 = w2 * w2;
                    float w10 = w4 * w4 * w2;
                    res[q] = lgv[q] * (1.f - w10);
                }
                outp.x = res[0]; outp.y = res[1];
                *(float2*)(srow + gc) = outp;
            }
        }
    }
}

// -------------------------------------------------------------------------
// Row softmax over C=1000: one 256-thread block per row.
// -------------------------------------------------------------------------
__global__ void __launch_bounds__(256)
softmax_kernel(const float* __restrict__ sc, float* __restrict__ out) {
    const int row = blockIdx.x;
    const float* rp = sc + (size_t)row * C_CLS;
    const int tid = threadIdx.x;

    float v[4];
    float m = -1e30f;
#pragma unroll
    for (int i = 0; i < 4; i++) {
        int idx = tid + i * 256;
        v[i] = (idx < C_CLS) ? rp[idx] : -1e30f;
        m = fmaxf(m, v[i]);
    }
#pragma unroll
    for (int o = 16; o; o >>= 1) m = fmaxf(m, __shfl_xor_sync(0xffffffffu, m, o));

    __shared__ float red[8];
    if ((tid & 31) == 0) red[tid >> 5] = m;
    __syncthreads();
    float bm = red[0];
#pragma unroll
    for (int ww = 1; ww < 8; ww++) bm = fmaxf(bm, red[ww]);
    __syncthreads();

    float e[4];
    float s = 0.f;
#pragma unroll
    for (int i = 0; i < 4; i++) {
        e[i] = __expf(v[i] - bm);
        s += e[i];
    }
#pragma unroll
    for (int o = 16; o; o >>= 1) s += __shfl_xor_sync(0xffffffffu, s, o);
    if ((tid & 31) == 0) red[tid >> 5] = s;
    __syncthreads();
    float total = 0.f;
#pragma unroll
    for (int ww = 0; ww < 8; ww++) total += red[ww];
    float inv = 1.f / total;

    float* orow = out + (size_t)row * C_CLS;
#pragma unroll
    for (int i = 0; i < 4; i++) {
        int idx = tid + i * 256;
        if (idx < C_CLS) orow[idx] = e[i] * inv;
    }
}

// -------------------------------------------------------------------------
extern "C" void kernel_launch(void* const* d_in, const int* in_sizes, int n_in,
                              void* d_out, int out_size) {
    const float* logits    = (const float*)d_in[0];  // [B, C]
    const float* features  = (const float*)d_in[1];  // [B, F]
    const float* mean_vecs = (const float*)d_in[2];  // [C, F]
    const float* wb_shape  = (const float*)d_in[3];  // [C]
    const float* wb_loc    = (const float*)d_in[4];  // [C]
    const float* wb_scale  = (const float*)d_in[5];  // [C]
    float* out = (float*)d_out;

    float *fr, *mr, *f2, *m2, *scores;
    cudaGetSymbolAddress((void**)&fr, g_fr);
    cudaGetSymbolAddress((void**)&mr, g_mr);
    cudaGetSymbolAddress((void**)&f2, g_f2);
    cudaGetSymbolAddress((void**)&m2, g_m2);
    cudaGetSymbolAddress((void**)&scores, g_scores);

    cudaFuncSetAttribute(gemm_openmax_tc,
                         cudaFuncAttributeMaxDynamicSharedMemorySize, SMEM_BYTES);

    convert_kernel<<<B_ROWS / 8, 256>>>(features, fr, f2, B_ROWS);
    convert_kernel<<<(C_CLS + 7) / 8, 256>>>(mean_vecs, mr, m2, C_CLS);

    dim3 grid((C_CLS + BN - 1) / BN, B_ROWS / BM);   // (8, 128)
    gemm_openmax_tc<<<grid, 256, SMEM_BYTES>>>(logits, wb_shape, wb_loc, wb_scale);

    softmax_kernel<<<B_ROWS, 256>>>(scores, out);
    (void)in_sizes; (void)n_in; (void)out_size;
}

// round 6
// speedup vs baseline: 1.1183x; 1.1183x over previous
#include <cuda_runtime.h>
#include <cuda_fp16.h>
#include <math.h>
#include <stdint.h>

#define B_ROWS 16384
#define C_CLS  1000
#define F_DIM  256

#define BM 128
#define BN 128
#define BK 32                   // halves per K chunk
#define NCHUNK (F_DIM / BK)     // 8
#define LDH 40                  // smem row stride in halves (pad 8)
#define TILE_HALVES (128 * LDH) // 5120 halves = 10240 B
#define BUF_HALVES  (2 * TILE_HALVES)
#define PARAM_OFF_H (2 * BUF_HALVES)          // after double buffers (in halves)
#define SMEM_BYTES  (PARAM_OFF_H * 2 + 2048)  // + 512 floats params

// ---- device scratch ----
__device__ __half g_fh[(size_t)B_ROWS * F_DIM];   // fp16 features
__device__ __half g_mh[(size_t)C_CLS * F_DIM];    // fp16 mean_vecs
__device__ float g_scores[(size_t)B_ROWS * C_CLS];
__device__ float g_f2[B_ROWS];
__device__ float g_m2[C_CLS];

__device__ __forceinline__ uint32_t smem_u32(const void* p) {
    uint32_t a;
    asm("{ .reg .u64 t; cvta.to.shared.u64 t, %1; cvt.u32.u64 %0, t; }" : "=r"(a) : "l"(p));
    return a;
}
__device__ __forceinline__ void cp16(uint32_t daddr, const void* src, uint32_t bytes) {
    asm volatile("cp.async.ca.shared.global [%0], [%1], 16, %2;"
                 :: "r"(daddr), "l"(src), "r"(bytes) : "memory");
}
__device__ __forceinline__ void mma_f16(float* d, const uint32_t* a, const uint32_t* b) {
    asm volatile(
        "mma.sync.aligned.m16n8k16.row.col.f32.f16.f16.f32 "
        "{%0,%1,%2,%3}, {%4,%5,%6,%7}, {%8,%9}, {%0,%1,%2,%3};"
        : "+f"(d[0]), "+f"(d[1]), "+f"(d[2]), "+f"(d[3])
        : "r"(a[0]), "r"(a[1]), "r"(a[2]), "r"(a[3]), "r"(b[0]), "r"(b[1]));
}

// -------------------------------------------------------------------------
// Convert fp32 -> fp16 and row sum-of-squares (fp32). One warp per row.
// -------------------------------------------------------------------------
__global__ void convert_kernel(const float* __restrict__ x,
                               __half* __restrict__ xh_out,
                               float* __restrict__ sq, int rows) {
    int warp = (blockIdx.x * blockDim.x + threadIdx.x) >> 5;
    int lane = threadIdx.x & 31;
    if (warp >= rows) return;
    const float* xr = x + (size_t)warp * F_DIM;
    float s = 0.f;
#pragma unroll
    for (int i = 0; i < 2; i++) {
        int e = (lane + i * 32) * 4;
        float4 v = *(const float4*)(xr + e);
        s += v.x * v.x + v.y * v.y + v.z * v.z + v.w * v.w;
        __half2 h0 = __floats2half2_rn(v.x, v.y);
        __half2 h1 = __floats2half2_rn(v.z, v.w);
        uint2 u;
        u.x = *(uint32_t*)&h0;
        u.y = *(uint32_t*)&h1;
        *(uint2*)(xh_out + (size_t)warp * F_DIM + e) = u;
    }
#pragma unroll
    for (int o = 16; o; o >>= 1) s += __shfl_xor_sync(0xffffffffu, s, o);
    if (lane == 0) sq[warp] = s;
}

// -------------------------------------------------------------------------
// fp16 mma.sync GEMM (features @ mean_vecs^T, fp32 accum) + OpenMax epilogue.
// 256 threads, CTA tile 128x128, BK=32 halves, double-buffered cp.async.
// -------------------------------------------------------------------------
__global__ void __launch_bounds__(256, 2)
gemm_openmax_tc(const float* __restrict__ logits,
                const float* __restrict__ wshape,
                const float* __restrict__ wloc,
                const float* __restrict__ wscale) {
    extern __shared__ __half smem[];
    const uint32_t sb = smem_u32(smem);
    const int tid = threadIdx.x;
    const int lane = tid & 31;
    const int wid = tid >> 5;
    const int wm = wid & 1;    // warp row (2 x 64)
    const int wn = wid >> 1;   // warp col (4 x 32)
    const int rowBase = blockIdx.y * BM;
    const int colBase = blockIdx.x * BN;

    float* m2s  = (float*)(smem + PARAM_OFF_H);
    float* shs  = m2s + 128;
    float* lcs  = shs + 128;
    float* iscs = lcs + 128;
    if (tid < 128) {
        int gc = colBase + tid;
        int cc = (gc < C_CLS) ? gc : 0;
        m2s[tid] = g_m2[cc];
        shs[tid] = wshape[cc];
        lcs[tid] = wloc[cc];
        iscs[tid] = 1.f / wscale[cc];
    }

    float acc[4][4][4];
#pragma unroll
    for (int i = 0; i < 4; i++)
#pragma unroll
        for (int j = 0; j < 4; j++)
#pragma unroll
            for (int q = 0; q < 4; q++) acc[i][j][q] = 0.f;

    // ---- async load of one K-chunk (A + B tiles) into buffer `buf` ----
    // Each tile: 128 rows x 32 halves (64B = 4 x 16B quarters per row).
    auto loadChunk = [&](int ch, int buf) {
        const int k0 = ch * BK;
        const uint32_t sa = sb + (uint32_t)buf * BUF_HALVES * 2;
        const uint32_t sbB = sa + TILE_HALVES * 2;
#pragma unroll
        for (int it = 0; it < 2; it++) {
            int idx = tid + it * 256;       // 0..511
            int r = idx >> 2;               // 0..127
            int q8 = (idx & 3) * 8;         // half offset 0,8,16,24
            const __half* gA = g_fh + (size_t)(rowBase + r) * F_DIM + k0 + q8;
            cp16(sa + (uint32_t)(r * LDH + q8) * 2, gA, 16u);
        }
#pragma unroll
        for (int it = 0; it < 2; it++) {
            int idx = tid + it * 256;
            int r = idx >> 2;
            int q8 = (idx & 3) * 8;
            int gc = colBase + r;
            const __half* gB = g_mh + (size_t)((gc < C_CLS) ? gc : 0) * F_DIM + k0 + q8;
            cp16(sbB + (uint32_t)(r * LDH + q8) * 2, gB, (gc < C_CLS) ? 16u : 0u);
        }
        asm volatile("cp.async.commit_group;" ::: "memory");
    };

    loadChunk(0, 0);

    const int g = lane >> 2;       // fragment row/col group 0..7
    const int kq = lane & 3;       // k quad
    const int r0 = wm * 64 + g;
    const int c0 = wn * 32 + g;

#pragma unroll 1
    for (int ch = 0; ch < NCHUNK; ch++) {
        if (ch + 1 < NCHUNK) {
            loadChunk(ch + 1, (ch + 1) & 1);
            asm volatile("cp.async.wait_group 1;" ::: "memory");
        } else {
            asm volatile("cp.async.wait_group 0;" ::: "memory");
        }
        __syncthreads();

        const __half* A = smem + (ch & 1) * BUF_HALVES;
        const __half* Bs = A + TILE_HALVES;
#pragma unroll
        for (int ks = 0; ks < 2; ks++) {
            const int kb = ks * 16 + 2 * kq;   // half index of this lane's k-pair
            uint32_t a[4][4], b[4][2];
#pragma unroll
            for (int ma = 0; ma < 4; ma++) {
                const __half* ap = A + (r0 + ma * 16) * LDH + kb;
                a[ma][0] = *(const uint32_t*)(ap);
                a[ma][1] = *(const uint32_t*)(ap + 8 * LDH);
                a[ma][2] = *(const uint32_t*)(ap + 8);
                a[ma][3] = *(const uint32_t*)(ap + 8 * LDH + 8);
            }
#pragma unroll
            for (int na = 0; na < 4; na++) {
                const __half* bp = Bs + (c0 + na * 8) * LDH + kb;
                b[na][0] = *(const uint32_t*)(bp);
                b[na][1] = *(const uint32_t*)(bp + 8);
            }
#pragma unroll
            for (int ma = 0; ma < 4; ma++)
#pragma unroll
                for (int na = 0; na < 4; na++)
                    mma_f16(acc[ma][na], a[ma], b[na]);
        }
        __syncthreads();
    }

    // ---- fused OpenMax epilogue ----
    const int lq = lane & 3;
    const int lr = lane >> 2;
#pragma unroll
    for (int ma = 0; ma < 4; ma++) {
#pragma unroll
        for (int h = 0; h < 2; h++) {
            const int grow = rowBase + wm * 64 + ma * 16 + lr + h * 8;
            const float f2v = g_f2[grow];
            const float* lrow = logits + (size_t)grow * C_CLS;
            float* srow = g_scores + (size_t)grow * C_CLS;
#pragma unroll
            for (int na = 0; na < 4; na++) {
                const int col = wn * 32 + na * 8 + 2 * lq;
                const int gc = colBase + col;
                if (gc >= C_CLS) continue;   // C even -> pair fully in/out
                float2 lg = *(const float2*)(lrow + gc);
                float dots[2] = { acc[ma][na][h * 2], acc[ma][na][h * 2 + 1] };
                float lgv[2] = { lg.x, lg.y };
                float res[2];
#pragma unroll
                for (int q = 0; q < 2; q++) {
                    const int c = col + q;
                    float d2 = f2v + m2s[c] - 2.f * dots[q];
                    float dist = sqrtf(fmaxf(d2, 1e-12f));
                    float xp = (dist - lcs[c]) * iscs[c];
                    float wv = 0.f;
                    if (xp > 0.f) {
                        float p = exp2f(shs[c] * __log2f(xp));
                        wv = 1.f - __expf(-p);
                    }
                    float w2 = wv * wv;
                    float w4 = w2 * w2;
                    float w10 = w4 * w4 * w2;
                    res[q] = lgv[q] * (1.f - w10);
                }
                float2 outp; outp.x = res[0]; outp.y = res[1];
                *(float2*)(srow + gc) = outp;
            }
        }
    }
}

// -------------------------------------------------------------------------
// Row softmax over C=1000: one 256-thread block per row.
// -------------------------------------------------------------------------
__global__ void __launch_bounds__(256)
softmax_kernel(const float* __restrict__ sc, float* __restrict__ out) {
    const int row = blockIdx.x;
    const float* rp = sc + (size_t)row * C_CLS;
    const int tid = threadIdx.x;

    float v[4];
    float m = -1e30f;
#pragma unroll
    for (int i = 0; i < 4; i++) {
        int idx = tid + i * 256;
        v[i] = (idx < C_CLS) ? rp[idx] : -1e30f;
        m = fmaxf(m, v[i]);
    }
#pragma unroll
    for (int o = 16; o; o >>= 1) m = fmaxf(m, __shfl_xor_sync(0xffffffffu, m, o));

    __shared__ float red[8];
    if ((tid & 31) == 0) red[tid >> 5] = m;
    __syncthreads();
    float bm = red[0];
#pragma unroll
    for (int ww = 1; ww < 8; ww++) bm = fmaxf(bm, red[ww]);
    __syncthreads();

    float e[4];
    float s = 0.f;
#pragma unroll
    for (int i = 0; i < 4; i++) {
        e[i] = __expf(v[i] - bm);
        s += e[i];
    }
#pragma unroll
    for (int o = 16; o; o >>= 1) s += __shfl_xor_sync(0xffffffffu, s, o);
    if ((tid & 31) == 0) red[tid >> 5] = s;
    __syncthreads();
    float total = 0.f;
#pragma unroll
    for (int ww = 0; ww < 8; ww++) total += red[ww];
    float inv = 1.f / total;

    float* orow = out + (size_t)row * C_CLS;
#pragma unroll
    for (int i = 0; i < 4; i++) {
        int idx = tid + i * 256;
        if (idx < C_CLS) orow[idx] = e[i] * inv;
    }
}

// -------------------------------------------------------------------------
extern "C" void kernel_launch(void* const* d_in, const int* in_sizes, int n_in,
                              void* d_out, int out_size) {
    const float* logits    = (const float*)d_in[0];  // [B, C]
    const float* features  = (const float*)d_in[1];  // [B, F]
    const float* mean_vecs = (const float*)d_in[2];  // [C, F]
    const float* wb_shape  = (const float*)d_in[3];  // [C]
    const float* wb_loc    = (const float*)d_in[4];  // [C]
    const float* wb_scale  = (const float*)d_in[5];  // [C]
    float* out = (float*)d_out;

    __half *fh, *mh;
    float *f2, *m2, *scores;
    cudaGetSymbolAddress((void**)&fh, g_fh);
    cudaGetSymbolAddress((void**)&mh, g_mh);
    cudaGetSymbolAddress((void**)&f2, g_f2);
    cudaGetSymbolAddress((void**)&m2, g_m2);
    cudaGetSymbolAddress((void**)&scores, g_scores);

    cudaFuncSetAttribute(gemm_openmax_tc,
                         cudaFuncAttributeMaxDynamicSharedMemorySize, SMEM_BYTES);

    convert_kernel<<<B_ROWS / 8, 256>>>(features, fh, f2, B_ROWS);
    convert_kernel<<<(C_CLS + 7) / 8, 256>>>(mean_vecs, mh, m2, C_CLS);

    dim3 grid((C_CLS + BN - 1) / BN, B_ROWS / BM);   // (8, 128)
    gemm_openmax_tc<<<grid, 256, SMEM_BYTES>>>(logits, wb_shape, wb_loc, wb_scale);

    softmax_kernel<<<B_ROWS, 256>>>(scores, out);
    (void)in_sizes; (void)n_in; (void)out_size;
}